// round 17
// baseline (speedup 1.0000x reference)
#include <cuda_runtime.h>

#define BB   2
#define NN   16384
#define MM   4096
#define CF   256
#define CT   128
#define CP   64
#define CTOT 384
#define SEG  4
#define SEGM (MM / SEG)   // 1024
#define PTS  16

#define KNN_BLOCKS (BB * (NN / 128) * SEG)              // 1024
#define TR_BLOCKS  (BB * (MM / 32) * (CTOT / 32))       // 3072

// ---- scratch (device globals; no allocation allowed) ----------------------
__device__ float g_pd[BB * NN * SEG * 3];   // partial top-3 shifted distances
__device__ int   g_pi[BB * NN * SEG * 3];   // partial top-3 indices
__device__ float g_featT[(size_t)BB * MM * CTOT];

#define INS3(d0, d1, d2, i0, i1, i2, dv, iv)                                   \
    if (dv < d2) {                                                             \
        if (dv < d1) {                                                         \
            d2 = d1; i2 = i1;                                                  \
            if (dv < d0) { d1 = d0; i1 = i0; d0 = dv; i0 = iv; }               \
            else         { d1 = dv; i1 = iv; }                                 \
        } else { d2 = dv; i2 = iv; }                                           \
    }

// ---------------------------------------------------------------------------
// Kernel 1 (fused grid): blocks [0, KNN_BLOCKS) do partial 3-NN (R5-proven
// config: 1 pt/lane, broadcast LDS, SEG=4) with a PAIR-GUARDED inner loop;
// blocks [KNN_BLOCKS, +TR_BLOCKS) transpose ref_features+ref_t_embed into
// channel-contiguous g_featT. The mem-bound transpose blocks overlap the
// compute-bound knn blocks inside one launch.
// ---------------------------------------------------------------------------
__global__ __launch_bounds__(128) void knn_tr_kernel(const float* __restrict__ coords,
                                                     const float* __restrict__ refc,
                                                     const float* __restrict__ rf,
                                                     const float* __restrict__ rt) {
    __shared__ float smem_u[SEGM * 4];   // 16 KB: float4 sref OR 32x33 tile+pad

    int tid = threadIdx.x;

    if (blockIdx.x < KNN_BLOCKS) {
        // ---------------- 3-NN partial ----------------
        float4* sref = (float4*)smem_u;
        int bid  = blockIdx.x;
        int seg  = bid & (SEG - 1);
        int rest = bid >> 2;
        int b    = rest >> 7;
        int pt   = ((rest & 127) << 7) + tid;

        const float* cp = coords + ((size_t)(b * NN + pt)) * 3;
        float px = cp[0], py = cp[1], pz = cp[2];
        float px2 = -2.0f * px, py2 = -2.0f * py, pz2 = -2.0f * pz;

        const float* rb = refc + ((size_t)b * MM + seg * SEGM) * 3;
        for (int m = tid; m < SEGM; m += 128) {
            const float* r = rb + (size_t)m * 3;
            float rx = r[0], ry = r[1], rz = r[2];
            sref[m] = make_float4(rx, ry, rz, rx * rx + ry * ry + rz * rz);
        }
        __syncthreads();

        float d0 = 1e30f, d1 = 1e30f, d2 = 1e30f;
        int   i0 = 0, i1 = 0, i2 = 0;
        int   gbase = seg * SEGM;

        #pragma unroll 4
        for (int m = 0; m < SEGM; m += 2) {
            float4 r1 = sref[m];
            float4 r2 = sref[m + 1];
            float dp1 = fmaf(r1.x, px2, fmaf(r1.y, py2, fmaf(r1.z, pz2, r1.w)));
            float dp2 = fmaf(r2.x, px2, fmaf(r2.y, py2, fmaf(r2.z, pz2, r2.w)));
            if (fminf(dp1, dp2) < d2) {
                INS3(d0, d1, d2, i0, i1, i2, dp1, gbase + m);
                INS3(d0, d1, d2, i0, i1, i2, dp2, gbase + m + 1);
            }
        }

        size_t base = (((size_t)(b * NN + pt)) * SEG + seg) * 3;
        g_pd[base]     = d0;  g_pi[base]     = i0;
        g_pd[base + 1] = d1;  g_pi[base + 1] = i1;
        g_pd[base + 2] = d2;  g_pi[base + 2] = i2;
    } else {
        // ---------------- transpose ----------------
        float (*tile)[33] = (float (*)[33])smem_u;
        int id    = blockIdx.x - KNN_BLOCKS;
        int perB  = (MM / 32) * (CTOT / 32);        // 1536
        int b     = id / perB;
        int rem   = id % perB;
        int mBase = (rem % (MM / 32)) * 32;
        int cBase = (rem / (MM / 32)) * 32;
        int tx = tid & 31;
        int ty = tid >> 5;                          // 0..3

        #pragma unroll
        for (int i = 0; i < 8; i++) {
            int c = cBase + ty + i * 4;
            int m = mBase + tx;
            float v;
            if (c < CF) v = rf[((size_t)b * CF + c) * MM + m];
            else        v = rt[((size_t)b * CT + (c - CF)) * MM + m];
            tile[ty + i * 4][tx] = v;
        }
        __syncthreads();
        #pragma unroll
        for (int i = 0; i < 8; i++) {
            int m = mBase + ty + i * 4;
            int c = cBase + tx;
            g_featT[((size_t)b * MM + m) * CTOT + c] = tile[tx][ty + i * 4];
        }
    }
}

// ---------------------------------------------------------------------------
// Kernel 2 (fused): per-point partial merge (float, exact R5 math) +
// inverse-distance weights + weighted float4 gather + transposed coalesced
// writes + points_features skip-copy.
// ---------------------------------------------------------------------------
__global__ __launch_bounds__(256) void interp_kernel(const float* __restrict__ coords,
                                                     const float* __restrict__ pf,
                                                     float* __restrict__ out) {
    __shared__ float sacc[PTS * (CTOT + 1)];
    __shared__ int   sidx[PTS * 3];
    __shared__ float sw[PTS * 3];

    int tid = threadIdx.x;
    int blocksPerB = NN / PTS;           // 1024
    int b  = blockIdx.x / blocksPerB;
    int n0 = (blockIdx.x % blocksPerB) * PTS;

    if (tid < PTS) {
        int pt = n0 + tid;
        size_t pbase = ((size_t)(b * NN + pt)) * SEG * 3;

        float d0 = 1e30f, d1 = 1e30f, d2 = 1e30f;
        int   i0 = 0, i1 = 0, i2 = 0;
        #pragma unroll
        for (int s = 0; s < SEG * 3; s++) {
            float dv = g_pd[pbase + s];
            int   iv = g_pi[pbase + s];
            INS3(d0, d1, d2, i0, i1, i2, dv, iv);
        }

        const float* cp = coords + ((size_t)(b * NN + pt)) * 3;
        float px = cp[0], py = cp[1], pz = cp[2];
        float pp = px * px + py * py + pz * pz;
        d0 += pp; d1 += pp; d2 += pp;

        float w0 = 1.0f / (d0 + 1e-8f);
        float w1 = 1.0f / (d1 + 1e-8f);
        float w2 = 1.0f / (d2 + 1e-8f);
        float inv = 1.0f / (w0 + w1 + w2);
        sw[tid * 3]     = w0 * inv;
        sw[tid * 3 + 1] = w1 * inv;
        sw[tid * 3 + 2] = w2 * inv;
        sidx[tid * 3]     = i0;
        sidx[tid * 3 + 1] = i1;
        sidx[tid * 3 + 2] = i2;
    }
    __syncthreads();

    const float4* ft = (const float4*)(g_featT + (size_t)b * MM * CTOT);
    const int R4 = CTOT / 4;             // 96

    for (int j = tid; j < PTS * R4; j += 256) {
        int nl = j / R4;
        int c4 = j - nl * R4;
        int q  = nl * 3;
        float w0 = sw[q], w1 = sw[q + 1], w2 = sw[q + 2];
        float4 a  = ft[(size_t)sidx[q]     * R4 + c4];
        float4 bv = ft[(size_t)sidx[q + 1] * R4 + c4];
        float4 cv = ft[(size_t)sidx[q + 2] * R4 + c4];
        float* dst = sacc + nl * (CTOT + 1) + c4 * 4;
        dst[0] = fmaf(w0, a.x, fmaf(w1, bv.x, w2 * cv.x));
        dst[1] = fmaf(w0, a.y, fmaf(w1, bv.y, w2 * cv.y));
        dst[2] = fmaf(w0, a.z, fmaf(w1, bv.z, w2 * cv.z));
        dst[3] = fmaf(w0, a.w, fmaf(w1, bv.w, w2 * cv.w));
    }
    __syncthreads();

    float* tout = out + (size_t)BB * 320 * NN;   // t_embed block after features
    for (int j = tid; j < PTS * CTOT; j += 256) {
        int c  = j >> 4;
        int nl = j & 15;
        float v = sacc[nl * (CTOT + 1) + c];
        if (c < CF) out[((size_t)b * 320 + c) * NN + n0 + nl] = v;
        else        tout[((size_t)b * CT + (c - CF)) * NN + n0 + nl] = v;
    }

    // skip-feature concat: channels 256..319 = points_features
    for (int j = tid; j < PTS * CP; j += 256) {
        int c  = j >> 4;
        int nl = j & 15;
        out[((size_t)b * 320 + 256 + c) * NN + n0 + nl] =
            pf[((size_t)b * CP + c) * NN + n0 + nl];
    }
}

// ---------------------------------------------------------------------------
extern "C" void kernel_launch(void* const* d_in, const int* in_sizes, int n_in,
                              void* d_out, int out_size) {
    const float* coords = (const float*)d_in[0];   // [B, N, 3]
    const float* refc   = (const float*)d_in[1];   // [B, M, 3]
    const float* rf     = (const float*)d_in[2];   // [B, 256, M]
    const float* rt     = (const float*)d_in[3];   // [B, 128, M]
    const float* pf     = (const float*)d_in[4];   // [B, 64, N]
    float* out = (float*)d_out;

    knn_tr_kernel<<<KNN_BLOCKS + TR_BLOCKS, 128>>>(coords, refc, rf, rt);

    interp_kernel<<<BB * NN / PTS, 256>>>(coords, pf, out);
}